// round 9
// baseline (speedup 1.0000x reference)
#include <cuda_runtime.h>
#include <cuda_fp16.h>
#include <cstdint>

// ---------------- problem constants ----------------
#define M_ 4096
#define K_ 4096
#define N_ 11008
#define G_ 128

#define KITERS 64            // K_/64 k-chunks
#define MT_ 32               // M_/128 activation tiles
#define NT_ 43               // N_/256 weight tiles
#define NTILES (NT_ * MT_)   // 1376
#define FULLS  1332          // 148 * 9 full tiles
#define HALves (NTILES - FULLS)          // 44 leftover -> 88 half tiles
#define GRID_GEMM (FULLS + 2 * HALves)   // 1420

#define A_TILE_BYTES 16384   // 128 rows (m) x 128B (64 fp16 k)
#define W_SMEM_BYTES 32768   // 256 rows (n) x 128B
#define STAGE_BYTES  (W_SMEM_BYTES + A_TILE_BYTES)   // 49152
#define STAGES 4
#define OFF_CTRL   (STAGES * STAGE_BYTES)            // 196608
#define OFF_FULL   (OFF_CTRL)
#define OFF_DONE   (OFF_FULL + 8 * STAGES)
#define SMEM_TOTAL (OFF_CTRL + 128)

#define SWZ(off) ((off) ^ (((off) >> 3) & 0x70))

// ---------------- scratch (static device array: allocation-free) ----------------
__device__ __align__(1024) __half g_a[(size_t)M_ * K_];   // ~32 MB, [mt][kc][swz 128x128B]

// ---------------- PTX helpers (base sm_103-safe) ----------------
__device__ __forceinline__ uint32_t smem_u32(const void* p) {
    uint32_t a;
    asm("{ .reg .u64 t; cvta.to.shared.u64 t, %1; cvt.u32.u64 %0, t; }" : "=r"(a) : "l"(p));
    return a;
}

#define MB_INIT(mbar, cnt) \
    asm volatile("mbarrier.init.shared.b64 [%0], %1;" :: "r"(mbar), "r"(cnt) : "memory")

#define MB_ARRIVE(mbar) \
    asm volatile("mbarrier.arrive.shared.b64 _, [%0];" :: "r"(mbar) : "memory")

#define MB_EXPECT_TX(mbar, bytes) \
    asm volatile("mbarrier.arrive.expect_tx.shared.b64 _, [%0], %1;" :: "r"(mbar), "r"(bytes) : "memory")

#define MB_WAIT(mbar, ph) do { \
    asm volatile("{\n\t.reg .pred P;\n\t" \
        "WL%=:\n\t" \
        "mbarrier.try_wait.parity.acquire.cta.shared::cta.b64 P, [%0], %1, 0x989680;\n\t" \
        "@P bra WD%=;\n\t" \
        "bra WL%=;\n\t" \
        "WD%=:\n\t}" :: "r"(mbar), "r"(ph) : "memory"); \
} while (0)

#define BULK_G2S(dst, src, bytes, mbar) \
    asm volatile("cp.async.bulk.shared::cluster.global.mbarrier::complete_tx::bytes [%0], [%1], %2, [%3];" \
        :: "r"(dst), "l"(src), "r"(bytes), "r"(mbar) : "memory")

#define LDSM4(r0, r1, r2, r3, addr) \
    asm volatile("ldmatrix.sync.aligned.m8n8.x4.shared.b16 {%0,%1,%2,%3}, [%4];" \
        : "=r"(r0), "=r"(r1), "=r"(r2), "=r"(r3) : "r"(addr))

#define MMA16816(acc, a0, a1, a2, a3, b0, b1) \
    asm volatile("mma.sync.aligned.m16n8k16.row.col.f32.f16.f16.f32 " \
        "{%0,%1,%2,%3}, {%4,%5,%6,%7}, {%8,%9}, {%0,%1,%2,%3};" \
        : "+f"((acc)[0]), "+f"((acc)[1]), "+f"((acc)[2]), "+f"((acc)[3]) \
        : "r"(a0), "r"(a1), "r"(a2), "r"(a3), "r"(b0), "r"(b1))

#define STS128(addr, r0, r1, r2, r3) \
    asm volatile("st.shared.v4.b32 [%0], {%1,%2,%3,%4};" \
        :: "r"(addr), "r"(r0), "r"(r1), "r"(r2), "r"(r3) : "memory")

__device__ __forceinline__ unsigned pack2(float a, float b) {
    __half2 h = __floats2half2_rn(a, b);
    return *reinterpret_cast<unsigned*>(&h);
}

// ---------------- prepass A: fp32 -> fp16, 128-row tile panels + SW128 ----------------
// grid (KITERS, MT_), 256 threads
__global__ void prep_a_kernel(const float* __restrict__ in) {
    int kc = blockIdx.x, mt = blockIdx.y, tid = threadIdx.x;
    char* dstbase = (char*)g_a + (size_t)(mt * KITERS + kc) * A_TILE_BYTES;
    int cc = tid & 7;
#pragma unroll
    for (int it = 0; it < 4; it++) {
        int r = (tid >> 3) + it * 32;                 // 0..127 (m local)
        int m = mt * 128 + r;
        int k0 = kc * 64 + cc * 8;
        const float4* p = (const float4*)(in + (size_t)m * K_ + k0);
        float4 f0 = p[0], f1 = p[1];
        uint4 v;
        v.x = pack2(f0.x, f0.y); v.y = pack2(f0.z, f0.w);
        v.z = pack2(f1.x, f1.y); v.w = pack2(f1.z, f1.w);
        *(uint4*)(dstbase + SWZ(r * 128 + cc * 16)) = v;
    }
}

// ---------------- GEMM body (templated on half-tile mode), sliced fused W dequant ----------------
// HALF=false: CTA 128(M) x 256(N), warp tile 64x64 (MI=4)
// HALF=true : CTA 128(M) x 128(N), warp tile 32x64 (MI=2)
template<bool HALF>
__device__ __forceinline__ void gemm_body(
    uint32_t sb,
    const int* __restrict__ q, const float* __restrict__ sc, const int* __restrict__ zp,
    const char* asrc, const float* __restrict__ bias, float* __restrict__ out,
    int nt, int mt, int halfsel)
{
    constexpr int MI = HALF ? 2 : 4;
    int tid = threadIdx.x, lane = tid & 31, wid = tid >> 5;
    int wm = HALF ? (wid & 3) : (wid & 1);
    int wn = HALF ? (wid >> 2) : (wid >> 1);

    uint32_t mb_full = sb + OFF_FULL;
    uint32_t mb_done = sb + OFF_DONE;

    bool act = HALF ? (tid < 128) : true;       // W-producer active?
    int n_l = HALF ? (tid & 127) : tid;          // local W smem row
    int n_g = nt * 256 + halfsel * 128 + n_l;    // global n of this thread's column

    // ---- prologue: produce W chunks 0..2 + A bulks 0..2 ----
#pragma unroll 1
    for (int p = 0; p < 3; p++) {
        uint32_t stgw = sb + p * STAGE_BYTES;
        if (act) {
            int goff = (p >> 1) * N_ + n_g;
            float s = __ldg(sc + goff);
            float zb = -(float)__ldg(zp + goff) * s;
            const int* qp = q + (size_t)p * 64 * N_ + n_g;
#pragma unroll 1
            for (int j = 0; j < 4; j++) {
                uint32_t h2[8];
#pragma unroll
                for (int t = 0; t < 8; t++) {
                    int q0 = __ldg(qp + (16 * j + 2 * t) * N_);
                    int q1 = __ldg(qp + (16 * j + 2 * t + 1) * N_);
                    h2[t] = pack2(fmaf((float)q0, s, zb), fmaf((float)q1, s, zb));
                }
                uint32_t ro = (uint32_t)n_l * 128 + j * 32;
                STS128(stgw + SWZ(ro), h2[0], h2[1], h2[2], h2[3]);
                STS128(stgw + SWZ(ro + 16), h2[4], h2[5], h2[6], h2[7]);
            }
        }
        if (tid == 0) {
            MB_EXPECT_TX(mb_full + 8 * p, (unsigned)A_TILE_BYTES);
            BULK_G2S(stgw + W_SMEM_BYTES, asrc + (size_t)p * A_TILE_BYTES,
                     (unsigned)A_TILE_BYTES, mb_full + 8 * p);
        }
        MB_ARRIVE(mb_full + 8 * p);
    }

    // per-thread ldmatrix row bases (stage-relative)
    uint32_t a_roff[MI], b_roff[4];
    uint32_t a_swz[MI], b_swz[4];
#pragma unroll
    for (int mi = 0; mi < MI; mi++) {
        int row = wm * (16 * MI) + mi * 16 + (lane & 15);
        a_roff[mi] = W_SMEM_BYTES + row * 128;        // A sits after W in stage
        a_swz[mi] = row & 7;
    }
#pragma unroll
    for (int nb = 0; nb < 4; nb++) {
        int row = wn * 64 + nb * 16 + (lane & 7) + ((lane >> 4) << 3);
        b_roff[nb] = row * 128;
        b_swz[nb] = row & 7;
    }
    uint32_t a_c = (lane >> 4);        // 0..1, A k-half within 16B cols
    uint32_t b_c = (lane >> 3) & 1;    // 0..1, B k-half

    float acc[MI][8][4];
#pragma unroll
    for (int mi = 0; mi < MI; mi++)
#pragma unroll
        for (int ni = 0; ni < 8; ni++)
#pragma unroll
            for (int e = 0; e < 4; e++) acc[mi][ni][e] = 0.f;

#pragma unroll 1
    for (int i = 0; i < KITERS; i++) {
        int s = i & 3, ph = (i >> 2) & 1;
        MB_WAIT(mb_full + 8 * s, ph);
        uint32_t stg = sb + s * STAGE_BYTES;

        int c2 = i + 3;                              // chunk being produced this iteration
        bool anyprod = (c2 < KITERS);
        bool produce = anyprod && act;
        int s2 = c2 & 3;                             // its stage slot == (i-1)&3
        uint32_t stg2 = sb + s2 * STAGE_BYTES;

        // gate: stage s2 must be fully consumed (all warps done chunk i-1)
        if (anyprod && i >= 1) MB_WAIT(mb_done + 8 * s2, ((i - 1) >> 2) & 1);

        float sS = 0.f, zB = 0.f;
        const int* qp = q;
        if (produce) {
            int goff = (c2 >> 1) * N_ + n_g;
            sS = __ldg(sc + goff);
            zB = -(float)__ldg(zp + goff) * sS;
            qp = q + (size_t)c2 * 64 * N_ + n_g;
        }
        int v[16];
        if (produce) {
#pragma unroll
            for (int t = 0; t < 16; t++) v[t] = __ldg(qp + t * N_);   // slice 0
        }

#pragma unroll
        for (int ks = 0; ks < 4; ks++) {
            uint32_t a[MI][4], b[4][4];
#pragma unroll
            for (int mi = 0; mi < MI; mi++) {
                uint32_t addr = stg + a_roff[mi] + (((ks * 2 + a_c) ^ a_swz[mi]) << 4);
                LDSM4(a[mi][0], a[mi][1], a[mi][2], a[mi][3], addr);
            }
#pragma unroll
            for (int nb = 0; nb < 4; nb++) {
                uint32_t addr = stg + b_roff[nb] + (((ks * 2 + b_c) ^ b_swz[nb]) << 4);
                LDSM4(b[nb][0], b[nb][1], b[nb][2], b[nb][3], addr);
            }
#pragma unroll
            for (int mi = 0; mi < MI; mi++)
#pragma unroll
                for (int ni = 0; ni < 8; ni++)
                    MMA16816(acc[mi][ni],
                             a[mi][0], a[mi][1], a[mi][2], a[mi][3],
                             b[ni >> 1][(ni & 1) * 2], b[ni >> 1][(ni & 1) * 2 + 1]);

            // ---- dequant slice ks: convert+store, then prefetch next slice ----
            if (produce) {
                uint32_t h2[8];
#pragma unroll
                for (int t = 0; t < 8; t++)
                    h2[t] = pack2(fmaf((float)v[2 * t], sS, zB),
                                  fmaf((float)v[2 * t + 1], sS, zB));
                uint32_t ro = (uint32_t)n_l * 128 + ks * 32;
                STS128(stg2 + SWZ(ro), h2[0], h2[1], h2[2], h2[3]);
                STS128(stg2 + SWZ(ro + 16), h2[4], h2[5], h2[6], h2[7]);
                if (ks < 3) {
#pragma unroll
                    for (int t = 0; t < 16; t++)
                        v[t] = __ldg(qp + ((ks + 1) * 16 + t) * N_);
                }
            }
            if (ks == 0 && anyprod && tid == 0) {
                MB_EXPECT_TX(mb_full + 8 * s2, (unsigned)A_TILE_BYTES);
                BULK_G2S(stg2 + W_SMEM_BYTES, asrc + (size_t)c2 * A_TILE_BYTES,
                         (unsigned)A_TILE_BYTES, mb_full + 8 * s2);
            }
        }

        if (lane == 0) MB_ARRIVE(mb_done + 8 * s);
        if (anyprod) MB_ARRIVE(mb_full + 8 * s2);
    }

    // ---- epilogue: streaming coalesced float2 stores + bias ----
    int m0 = mt * 128 + wm * (16 * MI) + (lane >> 2);
    int n0 = nt * 256 + halfsel * 128 + wn * 64 + (lane & 3) * 2;
#pragma unroll
    for (int ni = 0; ni < 8; ni++) {
        int n = n0 + ni * 8;
        float2 bb = *(const float2*)(bias + n);
#pragma unroll
        for (int mi = 0; mi < MI; mi++) {
            int m = m0 + mi * 16;
            float2 v0 = make_float2(acc[mi][ni][0] + bb.x, acc[mi][ni][1] + bb.y);
            float2 v1 = make_float2(acc[mi][ni][2] + bb.x, acc[mi][ni][3] + bb.y);
            __stcs((float2*)(out + (size_t)m * N_ + n), v0);
            __stcs((float2*)(out + (size_t)(m + 8) * N_ + n), v1);
        }
    }
}

// ---------------- GEMM kernel: 1332 full tiles + 88 half tiles (tail smoothing) ----------------
// grid GRID_GEMM, 256 threads (8 warps), dyn smem SMEM_TOTAL
__global__ void __launch_bounds__(256, 1)
gemm_kernel(const int* __restrict__ q, const float* __restrict__ sc, const int* __restrict__ zp,
            const float* __restrict__ bias, float* __restrict__ out) {
    extern __shared__ char smem[];
    uint32_t sb = smem_u32(smem);
    int tid = threadIdx.x;
    int bid = blockIdx.x;

    uint32_t mb_full = sb + OFF_FULL;
    uint32_t mb_done = sb + OFF_DONE;
    if (tid == 0) {
        for (int s = 0; s < STAGES; s++) { MB_INIT(mb_full + 8 * s, 257); MB_INIT(mb_done + 8 * s, 8); }
    }
    __syncthreads();

    if (bid < FULLS) {
        int t = bid;
        int nt = t >> 5, mt = t & 31;     // 32 consecutive bids share one q panel (L2 reuse)
        const char* asrc = (const char*)g_a + (size_t)mt * KITERS * A_TILE_BYTES;
        gemm_body<false>(sb, q, sc, zp, asrc, bias, out, nt, mt, 0);
    } else {
        int idx = bid - FULLS;            // 0..87
        int t = FULLS + (idx >> 1);       // 1332..1375
        int halfsel = idx & 1;
        int nt = t >> 5, mt = t & 31;
        const char* asrc = (const char*)g_a + (size_t)mt * KITERS * A_TILE_BYTES;
        gemm_body<true>(sb, q, sc, zp, asrc, bias, out, nt, mt, halfsel);
    }
}

// ---------------- launch ----------------
extern "C" void kernel_launch(void* const* d_in, const int* in_sizes, int n_in,
                              void* d_out, int out_size) {
    const float* input   = (const float*)d_in[0];
    const int*   qweight = (const int*)d_in[1];
    const float* scales  = (const float*)d_in[2];
    const int*   qzeros  = (const int*)d_in[3];
    const float* bias    = (const float*)d_in[4];
    float* out = (float*)d_out;

    cudaFuncSetAttribute(gemm_kernel, cudaFuncAttributeMaxDynamicSharedMemorySize, SMEM_TOTAL);

    prep_a_kernel<<<dim3(KITERS, MT_), 256>>>(input);
    gemm_kernel<<<GRID_GEMM, 256, SMEM_TOTAL>>>(qweight, scales, qzeros, bias, out);
}

// round 10
// speedup vs baseline: 2.1090x; 2.1090x over previous
#include <cuda_runtime.h>
#include <cuda_fp16.h>
#include <cstdint>

// ---------------- problem constants ----------------
#define M_ 4096
#define K_ 4096
#define N_ 11008
#define G_ 128

#define KITERS 64            // K_/64 k-chunks
#define MT_ 32               // M_/128 activation tiles
#define NT_ 43               // N_/256 weight tiles
#define NTILES (NT_ * MT_)   // 1376
#define FULLS  1332          // 148 * 9 full tiles
#define HALves (NTILES - FULLS)          // 44 leftover -> 88 half tiles
#define GRID_GEMM (FULLS + 2 * HALves)   // 1420

#define A_TILE_BYTES 16384   // 128 rows (m) x 128B (64 fp16 k)
#define W_TILE_BYTES 32768   // 256 rows (n) x 128B
#define STAGE_BYTES  (A_TILE_BYTES + W_TILE_BYTES)   // 49152
#define STAGES 4
#define OFF_CTRL   (STAGES * STAGE_BYTES)            // 196608
#define OFF_FULL   (OFF_CTRL)
#define OFF_DONE   (OFF_FULL + 8 * STAGES)
#define SMEM_TOTAL (OFF_CTRL + 128)

#define SWZ(off) ((off) ^ (((off) >> 3) & 0x70))

// ---------------- scratch (static device arrays: allocation-free) ----------------
__device__ __align__(1024) __half g_w[(size_t)K_ * N_];   // ~90 MB, [nt][kc][swz 256x128B]
__device__ __align__(1024) __half g_a[(size_t)M_ * K_];   // ~32 MB, [mt][kc][swz 128x128B]

// ---------------- PTX helpers (base sm_103-safe) ----------------
__device__ __forceinline__ uint32_t smem_u32(const void* p) {
    uint32_t a;
    asm("{ .reg .u64 t; cvta.to.shared.u64 t, %1; cvt.u32.u64 %0, t; }" : "=r"(a) : "l"(p));
    return a;
}

#define MB_INIT(mbar, cnt) \
    asm volatile("mbarrier.init.shared.b64 [%0], %1;" :: "r"(mbar), "r"(cnt) : "memory")

#define MB_ARRIVE(mbar) \
    asm volatile("mbarrier.arrive.shared.b64 _, [%0];" :: "r"(mbar) : "memory")

#define MB_EXPECT_TX(mbar, bytes) \
    asm volatile("mbarrier.arrive.expect_tx.shared.b64 _, [%0], %1;" :: "r"(mbar), "r"(bytes) : "memory")

#define MB_WAIT(mbar, ph) do { \
    asm volatile("{\n\t.reg .pred P;\n\t" \
        "WL%=:\n\t" \
        "mbarrier.try_wait.parity.acquire.cta.shared::cta.b64 P, [%0], %1, 0x989680;\n\t" \
        "@P bra WD%=;\n\t" \
        "bra WL%=;\n\t" \
        "WD%=:\n\t}" :: "r"(mbar), "r"(ph) : "memory"); \
} while (0)

#define BULK_G2S(dst, src, bytes, mbar) \
    asm volatile("cp.async.bulk.shared::cluster.global.mbarrier::complete_tx::bytes [%0], [%1], %2, [%3];" \
        :: "r"(dst), "l"(src), "r"(bytes), "r"(mbar) : "memory")

#define LDSM4(r0, r1, r2, r3, addr) \
    asm volatile("ldmatrix.sync.aligned.m8n8.x4.shared.b16 {%0,%1,%2,%3}, [%4];" \
        : "=r"(r0), "=r"(r1), "=r"(r2), "=r"(r3) : "r"(addr))

#define MMA16816(acc, a0, a1, a2, a3, b0, b1) \
    asm volatile("mma.sync.aligned.m16n8k16.row.col.f32.f16.f16.f32 " \
        "{%0,%1,%2,%3}, {%4,%5,%6,%7}, {%8,%9}, {%0,%1,%2,%3};" \
        : "+f"((acc)[0]), "+f"((acc)[1]), "+f"((acc)[2]), "+f"((acc)[3]) \
        : "r"(a0), "r"(a1), "r"(a2), "r"(a3), "r"(b0), "r"(b1))

#define STG_CS_V4(ptr, r0, r1, r2, r3) \
    asm volatile("st.global.cs.v4.b32 [%0], {%1,%2,%3,%4};" \
        :: "l"(ptr), "r"(r0), "r"(r1), "r"(r2), "r"(r3) : "memory")

__device__ __forceinline__ unsigned pack2(float a, float b) {
    __half2 h = __floats2half2_rn(a, b);
    return *reinterpret_cast<unsigned*>(&h);
}

// ---------------- prepass A: fp32 -> fp16, 128-row tile panels + SW128 ----------------
// grid (KITERS, MT_), 256 threads
__global__ void prep_a_kernel(const float* __restrict__ in) {
    int kc = blockIdx.x, mt = blockIdx.y, tid = threadIdx.x;
    char* dstbase = (char*)g_a + (size_t)(mt * KITERS + kc) * A_TILE_BYTES;
    int cc = tid & 7;
#pragma unroll
    for (int it = 0; it < 4; it++) {
        int r = (tid >> 3) + it * 32;                 // 0..127 (m local)
        int m = mt * 128 + r;
        int k0 = kc * 64 + cc * 8;
        const float4* p = (const float4*)(in + (size_t)m * K_ + k0);
        float4 f0 = p[0], f1 = p[1];
        uint4 v;
        v.x = pack2(f0.x, f0.y); v.y = pack2(f0.z, f0.w);
        v.z = pack2(f1.x, f1.y); v.w = pack2(f1.z, f1.w);
        *(uint4*)(dstbase + SWZ(r * 128 + cc * 16)) = v;
    }
}

// ---------------- prepass W: int4 dequant + transpose -> fp16 256-row tiles ----------------
// grid (KITERS, 86), 256 threads; each block handles 128 n-cols (half of a 256-row tile)
// q loads vectorized (int4), W writes streaming (st.global.cs)
__global__ void prep_w_kernel(const int* __restrict__ q,
                              const float* __restrict__ sc,
                              const int* __restrict__ zp) {
    __shared__ int   qs[64 * 129];
    __shared__ float scs[128];
    __shared__ float zps[128];
    int kc = blockIdx.x, nt2 = blockIdx.y, tid = threadIdx.x;
    int nt = nt2 >> 1, half = nt2 & 1;
    int g = kc >> 1;                                  // group of this 64-k chunk (G=128)
    if (tid < 128) {
        scs[tid] = sc[(size_t)g * N_ + nt2 * 128 + tid];
        zps[tid] = (float)zp[(size_t)g * N_ + nt2 * 128 + tid];
    }
    // 8192 ints = 2048 int4; 8 int4 per thread (16B-aligned: N_%4==0, base%128==0)
#pragma unroll
    for (int it = 0; it < 8; it++) {
        int e4 = tid + it * 256;                      // 0..2047
        int kl = e4 >> 5;                             // row 0..63 (32 int4 per row)
        int nl4 = e4 & 31;
        int4 v = *(const int4*)(q + (size_t)(kc * 64 + kl) * N_ + nt2 * 128 + nl4 * 4);
        int* d = &qs[kl * 129 + nl4 * 4];
        d[0] = v.x; d[1] = v.y; d[2] = v.z; d[3] = v.w;
    }
    __syncthreads();

    char* dstbase = (char*)g_w + (size_t)(nt * KITERS + kc) * W_TILE_BYTES;
    int cc = tid & 7;
#pragma unroll
    for (int it = 0; it < 4; it++) {
        int r = (tid >> 3) + it * 32;                 // 0..127 (n local within half)
        float s = scs[r], z = zps[r];
        unsigned u[4];
#pragma unroll
        for (int jj = 0; jj < 4; jj++) {
            int k0 = cc * 8 + jj * 2;
            float w0 = ((float)qs[(k0 + 0) * 129 + r] - z) * s;
            float w1 = ((float)qs[(k0 + 1) * 129 + r] - z) * s;
            u[jj] = pack2(w0, w1);
        }
        int row = half * 128 + r;                     // 0..255 (n local in tile)
        STG_CS_V4(dstbase + SWZ(row * 128 + cc * 16), u[0], u[1], u[2], u[3]);
    }
}

// ---------------- GEMM body (templated on half-tile mode) ----------------
// HALF=false: CTA 128(M) x 256(N), warp tile 64x64 (MI=4)
// HALF=true : CTA 128(M) x 128(N), warp tile 32x64 (MI=2); W half row-slice
template<bool HALF>
__device__ __forceinline__ void gemm_body(
    uint32_t sb, const char* wsrc, unsigned wbytes, const char* asrc,
    const float* __restrict__ bias, float* __restrict__ out,
    int nt, int mt, int halfsel)
{
    constexpr int MI = HALF ? 2 : 4;
    int tid = threadIdx.x, lane = tid & 31, wid = tid >> 5;
    int wm = HALF ? (wid & 3) : (wid & 1);
    int wn = HALF ? (wid >> 2) : (wid >> 1);

    uint32_t mb_full = sb + OFF_FULL;
    uint32_t mb_done = sb + OFF_DONE;
    unsigned stage_tx = wbytes + (unsigned)A_TILE_BYTES;

    if (tid == 0) {
#pragma unroll
        for (int p = 0; p < STAGES; p++) {
            MB_EXPECT_TX(mb_full + 8 * p, stage_tx);
            BULK_G2S(sb + p * STAGE_BYTES,
                     wsrc + (size_t)p * W_TILE_BYTES, wbytes, mb_full + 8 * p);
            BULK_G2S(sb + p * STAGE_BYTES + W_TILE_BYTES,
                     asrc + (size_t)p * A_TILE_BYTES, (unsigned)A_TILE_BYTES, mb_full + 8 * p);
        }
    }

    // per-thread ldmatrix row bases (stage-relative)
    uint32_t a_roff[MI], b_roff[4];
    uint32_t a_swz[MI], b_swz[4];
#pragma unroll
    for (int mi = 0; mi < MI; mi++) {
        int row = wm * (16 * MI) + mi * 16 + (lane & 15);
        a_roff[mi] = W_TILE_BYTES + row * 128;        // A sits after W in stage
        a_swz[mi] = row & 7;
    }
#pragma unroll
    for (int nb = 0; nb < 4; nb++) {
        int row = wn * 64 + nb * 16 + (lane & 7) + ((lane >> 4) << 3);
        b_roff[nb] = row * 128;
        b_swz[nb] = row & 7;
    }
    uint32_t a_c = (lane >> 4);        // 0..1, A k-half within 16B cols
    uint32_t b_c = (lane >> 3) & 1;    // 0..1, B k-half

    float acc[MI][8][4];
#pragma unroll
    for (int mi = 0; mi < MI; mi++)
#pragma unroll
        for (int ni = 0; ni < 8; ni++)
#pragma unroll
            for (int e = 0; e < 4; e++) acc[mi][ni][e] = 0.f;

#pragma unroll 1
    for (int i = 0; i < KITERS; i++) {
        int s = i & (STAGES - 1);
        MB_WAIT(mb_full + 8 * s, (i >> 2) & 1);
        uint32_t stg = sb + s * STAGE_BYTES;
#pragma unroll
        for (int ks = 0; ks < 4; ks++) {
            uint32_t a[MI][4], b[4][4];
#pragma unroll
            for (int mi = 0; mi < MI; mi++) {
                uint32_t addr = stg + a_roff[mi] + (((ks * 2 + a_c) ^ a_swz[mi]) << 4);
                LDSM4(a[mi][0], a[mi][1], a[mi][2], a[mi][3], addr);
            }
#pragma unroll
            for (int nb = 0; nb < 4; nb++) {
                uint32_t addr = stg + b_roff[nb] + (((ks * 2 + b_c) ^ b_swz[nb]) << 4);
                LDSM4(b[nb][0], b[nb][1], b[nb][2], b[nb][3], addr);
            }
#pragma unroll
            for (int mi = 0; mi < MI; mi++)
#pragma unroll
                for (int ni = 0; ni < 8; ni++)
                    MMA16816(acc[mi][ni],
                             a[mi][0], a[mi][1], a[mi][2], a[mi][3],
                             b[ni >> 1][(ni & 1) * 2], b[ni >> 1][(ni & 1) * 2 + 1]);
        }
        if (lane == 0) MB_ARRIVE(mb_done + 8 * s);
        if (tid == 0 && i + STAGES < KITERS) {
            MB_WAIT(mb_done + 8 * s, (i >> 2) & 1);   // all 8 warps done with this stage
            MB_EXPECT_TX(mb_full + 8 * s, stage_tx);
            BULK_G2S(sb + s * STAGE_BYTES,
                     wsrc + (size_t)(i + STAGES) * W_TILE_BYTES, wbytes, mb_full + 8 * s);
            BULK_G2S(sb + s * STAGE_BYTES + W_TILE_BYTES,
                     asrc + (size_t)(i + STAGES) * A_TILE_BYTES, (unsigned)A_TILE_BYTES, mb_full + 8 * s);
        }
    }

    // ---- epilogue: streaming coalesced float2 stores + bias ----
    int m0 = mt * 128 + wm * (16 * MI) + (lane >> 2);
    int n0 = nt * 256 + halfsel * 128 + wn * 64 + (lane & 3) * 2;
#pragma unroll
    for (int ni = 0; ni < 8; ni++) {
        int n = n0 + ni * 8;
        float2 bb = *(const float2*)(bias + n);
#pragma unroll
        for (int mi = 0; mi < MI; mi++) {
            int m = m0 + mi * 16;
            float2 v0 = make_float2(acc[mi][ni][0] + bb.x, acc[mi][ni][1] + bb.y);
            float2 v1 = make_float2(acc[mi][ni][2] + bb.x, acc[mi][ni][3] + bb.y);
            __stcs((float2*)(out + (size_t)m * N_ + n), v0);
            __stcs((float2*)(out + (size_t)(m + 8) * N_ + n), v1);
        }
    }
}

// ---------------- GEMM kernel: 1332 full tiles + 88 half tiles (tail smoothing) ----------------
// grid GRID_GEMM, 256 threads (8 warps), dyn smem SMEM_TOTAL
__global__ void __launch_bounds__(256, 1)
gemm_kernel(const float* __restrict__ bias, float* __restrict__ out) {
    extern __shared__ char smem[];
    uint32_t sb = smem_u32(smem);
    int tid = threadIdx.x;
    int bid = blockIdx.x;

    uint32_t mb_full = sb + OFF_FULL;
    uint32_t mb_done = sb + OFF_DONE;
    if (tid == 0) {
        for (int s = 0; s < STAGES; s++) { MB_INIT(mb_full + 8 * s, 1); MB_INIT(mb_done + 8 * s, 8); }
    }
    __syncthreads();

    if (bid < FULLS) {
        int t = bid;
        int nt = t >> 5, mt = t & 31;     // 32 consecutive bids share one W panel (L2 reuse)
        const char* wsrc = (const char*)g_w + (size_t)nt * KITERS * W_TILE_BYTES;
        const char* asrc = (const char*)g_a + (size_t)mt * KITERS * A_TILE_BYTES;
        gemm_body<false>(sb, wsrc, (unsigned)W_TILE_BYTES, asrc, bias, out, nt, mt, 0);
    } else {
        int idx = bid - FULLS;            // 0..87
        int t = FULLS + (idx >> 1);       // 1332..1375
        int halfsel = idx & 1;
        int nt = t >> 5, mt = t & 31;
        // W half-slice: rows [halfsel*128, +128) of the swizzled 256-row tile are the
        // contiguous 16KB at byte offset halfsel*16384 (swizzle is per-128B-row).
        const char* wsrc = (const char*)g_w + (size_t)nt * KITERS * W_TILE_BYTES
                         + (size_t)halfsel * (W_TILE_BYTES / 2);
        const char* asrc = (const char*)g_a + (size_t)mt * KITERS * A_TILE_BYTES;
        gemm_body<true>(sb, wsrc, (unsigned)(W_TILE_BYTES / 2), asrc, bias, out, nt, mt, halfsel);
    }
}

// ---------------- launch ----------------
extern "C" void kernel_launch(void* const* d_in, const int* in_sizes, int n_in,
                              void* d_out, int out_size) {
    const float* input   = (const float*)d_in[0];
    const int*   qweight = (const int*)d_in[1];
    const float* scales  = (const float*)d_in[2];
    const int*   qzeros  = (const int*)d_in[3];
    const float* bias    = (const float*)d_in[4];
    float* out = (float*)d_out;

    cudaFuncSetAttribute(gemm_kernel, cudaFuncAttributeMaxDynamicSharedMemorySize, SMEM_TOTAL);

    prep_a_kernel<<<dim3(KITERS, MT_), 256>>>(input);
    prep_w_kernel<<<dim3(KITERS, 86), 256>>>(qweight, scales, qzeros);
    gemm_kernel<<<GRID_GEMM, 256, SMEM_TOTAL>>>(bias, out);
}